// round 1
// baseline (speedup 1.0000x reference)
#include <cuda_runtime.h>
#include <math.h>

#define Nn 20000
#define Ee 320000
#define Hh 128
#define EFK 28     // edge_attr feature count (EF + K)
#define DIN 304    // 28 + 20 + 128 + 128

// Scratch (static device globals — no runtime allocation)
__device__ float g_t1[(size_t)Ee * Hh];   // relu(feat@W1+b1)
__device__ float g_mi[(size_t)Nn * Hh];   // segment_sum(mij*eij)
__device__ float g_dx[(size_t)Nn * 3];    // segment_sum(rel_x*xg)

// ---------------------------------------------------------------------------
__global__ __launch_bounds__(256) void zero_kernel() {
    int i = blockIdx.x * blockDim.x + threadIdx.x;
    if (i < Nn * Hh) g_mi[i] = 0.0f;
    if (i < Nn * 3)  g_dx[i] = 0.0f;
}

// ---------------------------------------------------------------------------
// E1: t1 = relu(feat @ W1 + b1),  feat = [edge_attr | rbf | h[dst] | h[src]]
// Tile: 64 edges x 128 outputs, K in 19 tiles of 16. 256 threads, 8x4 per thread.
__global__ __launch_bounds__(256) void e1_kernel(
    const float* __restrict__ h, const float* __restrict__ x,
    const float* __restrict__ ea, const float* __restrict__ w1,
    const float* __restrict__ b1, const int* __restrict__ eidx)
{
    __shared__ float As[64][17];
    __shared__ float Bs[16][128];
    __shared__ float sl2[64];
    __shared__ int   sdst[64], ssrc[64];

    const int tid = threadIdx.x;
    const int tx = tid & 31, ty = tid >> 5;
    const int ebase = blockIdx.x * 64;

    if (tid < 64) {
        int e = ebase + tid;
        int d = eidx[e], s = eidx[Ee + e];
        sdst[tid] = d; ssrc[tid] = s;
        float rx = x[d * 3 + 0] - x[s * 3 + 0];
        float ry = x[d * 3 + 1] - x[s * 3 + 1];
        float rz = x[d * 3 + 2] - x[s * 3 + 2];
        sl2[tid] = sqrtf(rx * rx + ry * ry + rz * rz);
    }
    __syncthreads();

    float acc[8][4];
#pragma unroll
    for (int i = 0; i < 8; i++)
#pragma unroll
        for (int j = 0; j < 4; j++) acc[i][j] = 0.0f;

    const float delta = 100.0f / 19.0f;
    const float coeff = -0.5f / (delta * delta);

    for (int kt = 0; kt < 19; kt++) {
        const int k0 = kt * 16;
        // A tile: 64x16
#pragma unroll
        for (int l = 0; l < 4; l++) {
            int idx = tid + l * 256;
            int r = idx >> 4, c = idx & 15;
            int cg = k0 + c;
            float v;
            if (cg < EFK) {
                v = ea[(size_t)(ebase + r) * EFK + cg];
            } else if (cg < EFK + 20) {
                int j = cg - EFK;
                float t = sl2[r] - (float)j * delta;
                v = expf(coeff * t * t);
            } else if (cg < 48 + Hh) {
                v = h[(size_t)sdst[r] * Hh + (cg - 48)];
            } else {
                v = h[(size_t)ssrc[r] * Hh + (cg - 48 - Hh)];
            }
            As[r][c] = v;
        }
        // B tile: 16x128
#pragma unroll
        for (int l = 0; l < 8; l++) {
            int idx = tid + l * 256;
            int kr = idx >> 7, cc = idx & 127;
            Bs[kr][cc] = w1[(size_t)(k0 + kr) * Hh + cc];
        }
        __syncthreads();
#pragma unroll
        for (int kk = 0; kk < 16; kk++) {
            float4 b = *(const float4*)&Bs[kk][tx * 4];
#pragma unroll
            for (int i = 0; i < 8; i++) {
                float a = As[ty + 8 * i][kk];
                acc[i][0] += a * b.x; acc[i][1] += a * b.y;
                acc[i][2] += a * b.z; acc[i][3] += a * b.w;
            }
        }
        __syncthreads();
    }

    float4 bb = *(const float4*)&b1[tx * 4];
#pragma unroll
    for (int i = 0; i < 8; i++) {
        int e = ebase + ty + 8 * i;
        float4 o;
        o.x = fmaxf(acc[i][0] + bb.x, 0.0f);
        o.y = fmaxf(acc[i][1] + bb.y, 0.0f);
        o.z = fmaxf(acc[i][2] + bb.z, 0.0f);
        o.w = fmaxf(acc[i][3] + bb.w, 0.0f);
        *(float4*)&g_t1[(size_t)e * Hh + tx * 4] = o;
    }
}

// ---------------------------------------------------------------------------
// E2: mij = relu(t1@W2+b2); eij = sigmoid(mij@inf_w+inf_b);
//     atomic mi[dst] += mij*eij;
//     u = relu(mij@xw1+xb1); xg = u@xw2+xb2; atomic dx[dst] += rel_x*xg
__global__ __launch_bounds__(256) void e2_kernel(
    const float* __restrict__ x,
    const float* __restrict__ w2, const float* __restrict__ b2,
    const float* __restrict__ infw, const float* __restrict__ infb,
    const float* __restrict__ xw1, const float* __restrict__ xb1,
    const float* __restrict__ xw2, const float* __restrict__ xb2,
    const int* __restrict__ eidx)
{
    __shared__ float As[64][17];
    __shared__ float Bs[16][128];
    __shared__ float Ms[64][129];
    __shared__ int   sdst[64];
    __shared__ float srel[64][3];

    const int tid = threadIdx.x;
    const int tx = tid & 31, ty = tid >> 5;
    const int ebase = blockIdx.x * 64;

    if (tid < 64) {
        int e = ebase + tid;
        int d = eidx[e], s = eidx[Ee + e];
        sdst[tid] = d;
        srel[tid][0] = x[d * 3 + 0] - x[s * 3 + 0];
        srel[tid][1] = x[d * 3 + 1] - x[s * 3 + 1];
        srel[tid][2] = x[d * 3 + 2] - x[s * 3 + 2];
    }
    __syncthreads();

    // --- GEMM1: t1 @ W2 ---
    float acc[8][4];
#pragma unroll
    for (int i = 0; i < 8; i++)
#pragma unroll
        for (int j = 0; j < 4; j++) acc[i][j] = 0.0f;

    for (int kt = 0; kt < 8; kt++) {
        const int k0 = kt * 16;
#pragma unroll
        for (int l = 0; l < 4; l++) {
            int idx = tid + l * 256;
            int r = idx >> 4, c = idx & 15;
            As[r][c] = g_t1[(size_t)(ebase + r) * Hh + k0 + c];
        }
#pragma unroll
        for (int l = 0; l < 8; l++) {
            int idx = tid + l * 256;
            int kr = idx >> 7, cc = idx & 127;
            Bs[kr][cc] = w2[(size_t)(k0 + kr) * Hh + cc];
        }
        __syncthreads();
#pragma unroll
        for (int kk = 0; kk < 16; kk++) {
            float4 b = *(const float4*)&Bs[kk][tx * 4];
#pragma unroll
            for (int i = 0; i < 8; i++) {
                float a = As[ty + 8 * i][kk];
                acc[i][0] += a * b.x; acc[i][1] += a * b.y;
                acc[i][2] += a * b.z; acc[i][3] += a * b.w;
            }
        }
        __syncthreads();
    }

    // mij = relu(acc + b2)
    float4 bb = *(const float4*)&b2[tx * 4];
#pragma unroll
    for (int i = 0; i < 8; i++) {
        acc[i][0] = fmaxf(acc[i][0] + bb.x, 0.0f);
        acc[i][1] = fmaxf(acc[i][1] + bb.y, 0.0f);
        acc[i][2] = fmaxf(acc[i][2] + bb.z, 0.0f);
        acc[i][3] = fmaxf(acc[i][3] + bb.w, 0.0f);
    }

    // eij per row (warp covers all 128 cols), then atomics into g_mi
    float4 iw = *(const float4*)&infw[tx * 4];
    float ib = infb[0];
#pragma unroll
    for (int i = 0; i < 8; i++) {
        int r = ty + 8 * i;
        float p = acc[i][0] * iw.x + acc[i][1] * iw.y +
                  acc[i][2] * iw.z + acc[i][3] * iw.w;
#pragma unroll
        for (int off = 16; off; off >>= 1) p += __shfl_xor_sync(0xFFFFFFFFu, p, off);
        float eij = 1.0f / (1.0f + expf(-(p + ib)));
        int d = sdst[r];
        float* mrow = &g_mi[(size_t)d * Hh + tx * 4];
        atomicAdd(&mrow[0], acc[i][0] * eij);
        atomicAdd(&mrow[1], acc[i][1] * eij);
        atomicAdd(&mrow[2], acc[i][2] * eij);
        atomicAdd(&mrow[3], acc[i][3] * eij);
        // stash mij into smem for GEMM2
        Ms[r][tx * 4 + 0] = acc[i][0];
        Ms[r][tx * 4 + 1] = acc[i][1];
        Ms[r][tx * 4 + 2] = acc[i][2];
        Ms[r][tx * 4 + 3] = acc[i][3];
    }
    __syncthreads();

    // --- GEMM2: mij @ xw1 (A from smem) ---
    float acc2[8][4];
#pragma unroll
    for (int i = 0; i < 8; i++)
#pragma unroll
        for (int j = 0; j < 4; j++) acc2[i][j] = 0.0f;

    for (int kt = 0; kt < 8; kt++) {
        const int k0 = kt * 16;
#pragma unroll
        for (int l = 0; l < 8; l++) {
            int idx = tid + l * 256;
            int kr = idx >> 7, cc = idx & 127;
            Bs[kr][cc] = xw1[(size_t)(k0 + kr) * Hh + cc];
        }
        __syncthreads();
#pragma unroll
        for (int kk = 0; kk < 16; kk++) {
            float4 b = *(const float4*)&Bs[kk][tx * 4];
#pragma unroll
            for (int i = 0; i < 8; i++) {
                float a = Ms[ty + 8 * i][k0 + kk];
                acc2[i][0] += a * b.x; acc2[i][1] += a * b.y;
                acc2[i][2] += a * b.z; acc2[i][3] += a * b.w;
            }
        }
        __syncthreads();
    }

    // xg = relu(acc2 + xb1) @ xw2 + xb2 ; atomics into g_dx
    float4 xb = *(const float4*)&xb1[tx * 4];
    float4 xw = *(const float4*)&xw2[tx * 4];
    float xb2v = xb2[0];
#pragma unroll
    for (int i = 0; i < 8; i++) {
        int r = ty + 8 * i;
        float u0 = fmaxf(acc2[i][0] + xb.x, 0.0f);
        float u1 = fmaxf(acc2[i][1] + xb.y, 0.0f);
        float u2 = fmaxf(acc2[i][2] + xb.z, 0.0f);
        float u3 = fmaxf(acc2[i][3] + xb.w, 0.0f);
        float q = u0 * xw.x + u1 * xw.y + u2 * xw.z + u3 * xw.w;
#pragma unroll
        for (int off = 16; off; off >>= 1) q += __shfl_xor_sync(0xFFFFFFFFu, q, off);
        if (tx == 0) {
            float xg = q + xb2v;
            int d = sdst[r];
            atomicAdd(&g_dx[(size_t)d * 3 + 0], srel[r][0] * xg);
            atomicAdd(&g_dx[(size_t)d * 3 + 1], srel[r][1] * xg);
            atomicAdd(&g_dx[(size_t)d * 3 + 2], srel[r][2] * xg);
        }
    }
}

// ---------------------------------------------------------------------------
// Node: out = relu([mi|h]@nw1+nb1)@nw2+nb2 ; x_new = x + dx/E
__global__ __launch_bounds__(256) void node_kernel(
    const float* __restrict__ h, const float* __restrict__ x,
    const float* __restrict__ nw1, const float* __restrict__ nb1,
    const float* __restrict__ nw2, const float* __restrict__ nb2,
    float* __restrict__ out)
{
    __shared__ float As[64][17];
    __shared__ float Bs[16][128];
    __shared__ float Ys[64][129];

    const int tid = threadIdx.x;
    const int tx = tid & 31, ty = tid >> 5;
    const int nbase = blockIdx.x * 64;

    // --- GEMM1: [mi|h] @ nw1, K = 256 ---
    float acc[8][4];
#pragma unroll
    for (int i = 0; i < 8; i++)
#pragma unroll
        for (int j = 0; j < 4; j++) acc[i][j] = 0.0f;

    for (int kt = 0; kt < 16; kt++) {
        const int k0 = kt * 16;
#pragma unroll
        for (int l = 0; l < 4; l++) {
            int idx = tid + l * 256;
            int r = idx >> 4, c = idx & 15;
            int n = nbase + r, cg = k0 + c;
            float v = 0.0f;
            if (n < Nn) {
                if (cg < Hh) v = g_mi[(size_t)n * Hh + cg];
                else         v = h[(size_t)n * Hh + (cg - Hh)];
            }
            As[r][c] = v;
        }
#pragma unroll
        for (int l = 0; l < 8; l++) {
            int idx = tid + l * 256;
            int kr = idx >> 7, cc = idx & 127;
            Bs[kr][cc] = nw1[(size_t)(k0 + kr) * Hh + cc];
        }
        __syncthreads();
#pragma unroll
        for (int kk = 0; kk < 16; kk++) {
            float4 b = *(const float4*)&Bs[kk][tx * 4];
#pragma unroll
            for (int i = 0; i < 8; i++) {
                float a = As[ty + 8 * i][kk];
                acc[i][0] += a * b.x; acc[i][1] += a * b.y;
                acc[i][2] += a * b.z; acc[i][3] += a * b.w;
            }
        }
        __syncthreads();
    }

    float4 bb = *(const float4*)&nb1[tx * 4];
#pragma unroll
    for (int i = 0; i < 8; i++) {
        int r = ty + 8 * i;
        Ys[r][tx * 4 + 0] = fmaxf(acc[i][0] + bb.x, 0.0f);
        Ys[r][tx * 4 + 1] = fmaxf(acc[i][1] + bb.y, 0.0f);
        Ys[r][tx * 4 + 2] = fmaxf(acc[i][2] + bb.z, 0.0f);
        Ys[r][tx * 4 + 3] = fmaxf(acc[i][3] + bb.w, 0.0f);
    }
    __syncthreads();

    // --- GEMM2: Ys @ nw2 ---
    float acc2[8][4];
#pragma unroll
    for (int i = 0; i < 8; i++)
#pragma unroll
        for (int j = 0; j < 4; j++) acc2[i][j] = 0.0f;

    for (int kt = 0; kt < 8; kt++) {
        const int k0 = kt * 16;
#pragma unroll
        for (int l = 0; l < 8; l++) {
            int idx = tid + l * 256;
            int kr = idx >> 7, cc = idx & 127;
            Bs[kr][cc] = nw2[(size_t)(k0 + kr) * Hh + cc];
        }
        __syncthreads();
#pragma unroll
        for (int kk = 0; kk < 16; kk++) {
            float4 b = *(const float4*)&Bs[kk][tx * 4];
#pragma unroll
            for (int i = 0; i < 8; i++) {
                float a = Ys[ty + 8 * i][k0 + kk];
                acc2[i][0] += a * b.x; acc2[i][1] += a * b.y;
                acc2[i][2] += a * b.z; acc2[i][3] += a * b.w;
            }
        }
        __syncthreads();
    }

    float4 b2v = *(const float4*)&nb2[tx * 4];
#pragma unroll
    for (int i = 0; i < 8; i++) {
        int n = nbase + ty + 8 * i;
        if (n < Nn) {
            float4 o;
            o.x = acc2[i][0] + b2v.x;
            o.y = acc2[i][1] + b2v.y;
            o.z = acc2[i][2] + b2v.z;
            o.w = acc2[i][3] + b2v.w;
            *(float4*)&out[(size_t)n * Hh + tx * 4] = o;
        }
    }

    // x update: 64 nodes x 3 coords
    if (tid < 192) {
        int nl = tid / 3, c = tid % 3;
        int n = nbase + nl;
        if (n < Nn) {
            out[(size_t)Nn * Hh + (size_t)n * 3 + c] =
                x[(size_t)n * 3 + c] + g_dx[(size_t)n * 3 + c] * (1.0f / (float)Ee);
        }
    }
}

// ---------------------------------------------------------------------------
extern "C" void kernel_launch(void* const* d_in, const int* in_sizes, int n_in,
                              void* d_out, int out_size) {
    const float* h    = (const float*)d_in[0];
    const float* x    = (const float*)d_in[1];
    const float* ea   = (const float*)d_in[2];
    const float* ew1  = (const float*)d_in[3];
    const float* eb1  = (const float*)d_in[4];
    const float* ew2  = (const float*)d_in[5];
    const float* eb2  = (const float*)d_in[6];
    const float* infw = (const float*)d_in[7];
    const float* infb = (const float*)d_in[8];
    const float* nw1  = (const float*)d_in[9];
    const float* nb1  = (const float*)d_in[10];
    const float* nw2  = (const float*)d_in[11];
    const float* nb2  = (const float*)d_in[12];
    const float* xw1  = (const float*)d_in[13];
    const float* xb1  = (const float*)d_in[14];
    const float* xw2  = (const float*)d_in[15];
    const float* xb2  = (const float*)d_in[16];
    const int*   eidx = (const int*)d_in[17];
    float* out = (float*)d_out;

    zero_kernel<<<(Nn * Hh + 255) / 256, 256>>>();
    e1_kernel<<<Ee / 64, 256>>>(h, x, ea, ew1, eb1, eidx);
    e2_kernel<<<Ee / 64, 256>>>(x, ew2, eb2, infw, infb, xw1, xb1, xw2, xb2, eidx);
    node_kernel<<<(Nn + 63) / 64, 256>>>(h, x, nw1, nb1, nw2, nb2, out);
}

// round 2
// speedup vs baseline: 2.1053x; 2.1053x over previous
#include <cuda_runtime.h>
#include <math.h>
#include <stdint.h>

#define Nn 20000
#define Ee 320000
#define Hh 128
#define EFK 28     // edge_attr feature count (EF + K)
#define DIN 304    // 28 + 20 + 128 + 128

// Scratch (static device globals — no runtime allocation)
__device__ float g_mi[(size_t)Nn * Hh];   // segment_sum(mij*eij)
__device__ float g_dx[(size_t)Nn * 3];    // segment_sum(rel_x*xg)

// ---------------------------------------------------------------------------
__global__ __launch_bounds__(256) void zero_kernel() {
    int i = blockIdx.x * blockDim.x + threadIdx.x;
    if (i < Nn * Hh) g_mi[i] = 0.0f;
    if (i < Nn * 3)  g_dx[i] = 0.0f;
}

// ---------------------------------------------------------------------------
__device__ __forceinline__ unsigned f2tf(float f) {
    unsigned u;
    asm("cvt.rna.tf32.f32 %0, %1;" : "=r"(u) : "f"(f));
    return u;
}

__device__ __forceinline__ void mma_tf32(float4& d,
    unsigned a0, unsigned a1, unsigned a2, unsigned a3,
    unsigned b0, unsigned b1)
{
    asm volatile(
        "mma.sync.aligned.m16n8k8.row.col.f32.tf32.tf32.f32 "
        "{%0,%1,%2,%3}, {%4,%5,%6,%7}, {%8,%9}, {%0,%1,%2,%3};\n"
        : "+f"(d.x), "+f"(d.y), "+f"(d.z), "+f"(d.w)
        : "r"(a0), "r"(a1), "r"(a2), "r"(a3), "r"(b0), "r"(b1));
}

__device__ __forceinline__ void red_add_v4(float* addr, float4 v) {
    asm volatile("red.global.add.v4.f32 [%0], {%1,%2,%3,%4};"
                 :: "l"(addr), "f"(v.x), "f"(v.y), "f"(v.z), "f"(v.w)
                 : "memory");
}

// ---------------------------------------------------------------------------
// Fused edge kernel (tensor-core tf32):
//   t1  = relu(feat @ W1 + b1)              feat = [edge_attr | rbf | h_dst | h_src]
//   mij = relu(t1 @ W2 + b2)
//   eij = sigmoid(mij @ inf_w + inf_b);  mi[dst] += mij*eij   (red.v4 atomics)
//   u   = relu(mij @ xw1 + xb1); xg = u @ xw2 + xb2; dx[dst] += rel_x*xg
// Tile: 64 edges x 128 cols, 256 threads = 8 warps (2x4 warp grid, 32x32/warp).
__global__ __launch_bounds__(256) void edge_kernel(
    const float* __restrict__ h, const float* __restrict__ x,
    const float* __restrict__ ea,
    const float* __restrict__ w1, const float* __restrict__ b1,
    const float* __restrict__ w2, const float* __restrict__ b2,
    const float* __restrict__ infw, const float* __restrict__ infb,
    const float* __restrict__ xw1, const float* __restrict__ xb1,
    const float* __restrict__ xw2, const float* __restrict__ xb2,
    const int* __restrict__ eidx)
{
    __shared__ float Ms[64][132];            // staging: tf32(t1) -> mij -> u
    __shared__ unsigned Bs[16][136];         // B tile (tf32 bits), conflict-free pad
    __shared__ int   sdst[64];
    __shared__ float srel[64][3];
    __shared__ float sl2[64];

    // As aliases the front of Ms (only live inside GEMM1 k-loop)
    unsigned (*As)[20] = reinterpret_cast<unsigned(*)[20]>(&Ms[0][0]);

    const int tid  = threadIdx.x;
    const int w    = tid >> 5;          // warp 0..7
    const int lane = tid & 31;
    const int qd   = lane >> 2;         // 0..7
    const int l4   = lane & 3;          // 0..3
    const int wm   = w >> 2;            // 0..1  (M tile of 32)
    const int wn   = w & 3;             // 0..3  (N tile of 32)
    const int R0   = wm * 32;
    const int C0   = wn * 32;
    const int ebase = blockIdx.x * 64;

    if (tid < 64) {
        int e = ebase + tid;
        int d = eidx[e], s = eidx[Ee + e];
        sdst[tid] = d;
        float rx = x[d * 3 + 0] - x[s * 3 + 0];
        float ry = x[d * 3 + 1] - x[s * 3 + 1];
        float rz = x[d * 3 + 2] - x[s * 3 + 2];
        srel[tid][0] = rx; srel[tid][1] = ry; srel[tid][2] = rz;
        sl2[tid] = sqrtf(rx * rx + ry * ry + rz * rz);
    }
    // note: h-gather indices live in registers of the filler threads only; we
    // re-read eidx inside the A-fill to avoid an extra smem array.
    __shared__ int ssrc[64];
    if (tid < 64) ssrc[tid] = eidx[Ee + ebase + tid];
    __syncthreads();

    float4 acc[2][4];
#pragma unroll
    for (int mt = 0; mt < 2; mt++)
#pragma unroll
        for (int nt = 0; nt < 4; nt++) acc[mt][nt] = make_float4(0.f, 0.f, 0.f, 0.f);

    const float delta = 100.0f / 19.0f;
    const float coeff = -0.5f / (delta * delta);

    // ---------------- GEMM1: feat(64x304) @ w1(304x128) ----------------
    for (int kt = 0; kt < 19; kt++) {
        const int k0 = kt * 16;
        __syncthreads();   // previous tile's frags consumed
        // A tile 64x16 (assembled feat, tf32)
#pragma unroll
        for (int l = 0; l < 4; l++) {
            int idx = tid + l * 256;
            int r = idx >> 4, c = idx & 15;
            int cg = k0 + c;
            float v;
            if (cg < EFK) {
                v = ea[(size_t)(ebase + r) * EFK + cg];
            } else if (cg < EFK + 20) {
                int j = cg - EFK;
                float t = sl2[r] - (float)j * delta;
                v = expf(coeff * t * t);
            } else if (cg < 48 + Hh) {
                v = h[(size_t)sdst[r] * Hh + (cg - 48)];
            } else {
                v = h[(size_t)ssrc[r] * Hh + (cg - 48 - Hh)];
            }
            As[r][c] = f2tf(v);
        }
        // B tile 16x128
#pragma unroll
        for (int l = 0; l < 8; l++) {
            int idx = tid + l * 256;
            int kr = idx >> 7, cc = idx & 127;
            Bs[kr][cc] = f2tf(w1[(size_t)(k0 + kr) * Hh + cc]);
        }
        __syncthreads();
#pragma unroll
        for (int ks = 0; ks < 16; ks += 8) {
            unsigned a[2][4], bfr[4][2];
#pragma unroll
            for (int mt = 0; mt < 2; mt++) {
                int r0 = R0 + mt * 16;
                a[mt][0] = As[r0 + qd][ks + l4];
                a[mt][1] = As[r0 + qd + 8][ks + l4];
                a[mt][2] = As[r0 + qd][ks + l4 + 4];
                a[mt][3] = As[r0 + qd + 8][ks + l4 + 4];
            }
#pragma unroll
            for (int nt = 0; nt < 4; nt++) {
                int c0 = C0 + nt * 8 + qd;
                bfr[nt][0] = Bs[ks + l4][c0];
                bfr[nt][1] = Bs[ks + l4 + 4][c0];
            }
#pragma unroll
            for (int mt = 0; mt < 2; mt++)
#pragma unroll
                for (int nt = 0; nt < 4; nt++)
                    mma_tf32(acc[mt][nt], a[mt][0], a[mt][1], a[mt][2], a[mt][3],
                             bfr[nt][0], bfr[nt][1]);
        }
    }
    __syncthreads();

    // Epilogue 1: relu(+b1), store tf32 into Ms
#pragma unroll
    for (int nt = 0; nt < 4; nt++) {
        int c = C0 + nt * 8 + 2 * l4;
        float bx = b1[c], by = b1[c + 1];
#pragma unroll
        for (int mt = 0; mt < 2; mt++) {
            int rA = R0 + mt * 16 + qd;
            Ms[rA][c]     = __uint_as_float(f2tf(fmaxf(acc[mt][nt].x + bx, 0.f)));
            Ms[rA][c + 1] = __uint_as_float(f2tf(fmaxf(acc[mt][nt].y + by, 0.f)));
            Ms[rA + 8][c]     = __uint_as_float(f2tf(fmaxf(acc[mt][nt].z + bx, 0.f)));
            Ms[rA + 8][c + 1] = __uint_as_float(f2tf(fmaxf(acc[mt][nt].w + by, 0.f)));
        }
    }
    __syncthreads();

    // ---------------- GEMM2: t1(64x128) @ w2(128x128) ----------------
#pragma unroll
    for (int mt = 0; mt < 2; mt++)
#pragma unroll
        for (int nt = 0; nt < 4; nt++) acc[mt][nt] = make_float4(0.f, 0.f, 0.f, 0.f);

    for (int kt = 0; kt < 8; kt++) {
        const int k0 = kt * 16;
        __syncthreads();
#pragma unroll
        for (int l = 0; l < 8; l++) {
            int idx = tid + l * 256;
            int kr = idx >> 7, cc = idx & 127;
            Bs[kr][cc] = f2tf(w2[(size_t)(k0 + kr) * Hh + cc]);
        }
        __syncthreads();
#pragma unroll
        for (int ks = 0; ks < 16; ks += 8) {
            unsigned a[2][4], bfr[4][2];
#pragma unroll
            for (int mt = 0; mt < 2; mt++) {
                int r0 = R0 + mt * 16;
                a[mt][0] = __float_as_uint(Ms[r0 + qd][k0 + ks + l4]);
                a[mt][1] = __float_as_uint(Ms[r0 + qd + 8][k0 + ks + l4]);
                a[mt][2] = __float_as_uint(Ms[r0 + qd][k0 + ks + l4 + 4]);
                a[mt][3] = __float_as_uint(Ms[r0 + qd + 8][k0 + ks + l4 + 4]);
            }
#pragma unroll
            for (int nt = 0; nt < 4; nt++) {
                int c0 = C0 + nt * 8 + qd;
                bfr[nt][0] = Bs[ks + l4][c0];
                bfr[nt][1] = Bs[ks + l4 + 4][c0];
            }
#pragma unroll
            for (int mt = 0; mt < 2; mt++)
#pragma unroll
                for (int nt = 0; nt < 4; nt++)
                    mma_tf32(acc[mt][nt], a[mt][0], a[mt][1], a[mt][2], a[mt][3],
                             bfr[nt][0], bfr[nt][1]);
        }
    }
    __syncthreads();   // all Ms reads done before overwrite

    // Epilogue 2: mij = relu(+b2), store fp32 into Ms
#pragma unroll
    for (int nt = 0; nt < 4; nt++) {
        int c = C0 + nt * 8 + 2 * l4;
        float bx = b2[c], by = b2[c + 1];
#pragma unroll
        for (int mt = 0; mt < 2; mt++) {
            int rA = R0 + mt * 16 + qd;
            Ms[rA][c]     = fmaxf(acc[mt][nt].x + bx, 0.f);
            Ms[rA][c + 1] = fmaxf(acc[mt][nt].y + by, 0.f);
            Ms[rA + 8][c]     = fmaxf(acc[mt][nt].z + bx, 0.f);
            Ms[rA + 8][c + 1] = fmaxf(acc[mt][nt].w + by, 0.f);
        }
    }
    __syncthreads();

    // eij + mi atomics: warp w handles rows w*8 .. w*8+7
    {
        float4 iw4 = *(const float4*)&infw[lane * 4];
        float ib = infb[0];
#pragma unroll
        for (int i = 0; i < 8; i++) {
            int r = w * 8 + i;
            float4 mv = *(const float4*)&Ms[r][lane * 4];
            float p = mv.x * iw4.x + mv.y * iw4.y + mv.z * iw4.z + mv.w * iw4.w;
#pragma unroll
            for (int off = 16; off; off >>= 1) p += __shfl_xor_sync(0xFFFFFFFFu, p, off);
            float eij = 1.0f / (1.0f + expf(-(p + ib)));
            int d = sdst[r];
            red_add_v4(&g_mi[(size_t)d * Hh + lane * 4],
                       make_float4(mv.x * eij, mv.y * eij, mv.z * eij, mv.w * eij));
        }
    }
    __syncthreads();

    // ---------------- GEMM3: mij(64x128) @ xw1(128x128) ----------------
#pragma unroll
    for (int mt = 0; mt < 2; mt++)
#pragma unroll
        for (int nt = 0; nt < 4; nt++) acc[mt][nt] = make_float4(0.f, 0.f, 0.f, 0.f);

    for (int kt = 0; kt < 8; kt++) {
        const int k0 = kt * 16;
        __syncthreads();
#pragma unroll
        for (int l = 0; l < 8; l++) {
            int idx = tid + l * 256;
            int kr = idx >> 7, cc = idx & 127;
            Bs[kr][cc] = f2tf(xw1[(size_t)(k0 + kr) * Hh + cc]);
        }
        __syncthreads();
#pragma unroll
        for (int ks = 0; ks < 16; ks += 8) {
            unsigned a[2][4], bfr[4][2];
#pragma unroll
            for (int mt = 0; mt < 2; mt++) {
                int r0 = R0 + mt * 16;
                a[mt][0] = f2tf(Ms[r0 + qd][k0 + ks + l4]);
                a[mt][1] = f2tf(Ms[r0 + qd + 8][k0 + ks + l4]);
                a[mt][2] = f2tf(Ms[r0 + qd][k0 + ks + l4 + 4]);
                a[mt][3] = f2tf(Ms[r0 + qd + 8][k0 + ks + l4 + 4]);
            }
#pragma unroll
            for (int nt = 0; nt < 4; nt++) {
                int c0 = C0 + nt * 8 + qd;
                bfr[nt][0] = Bs[ks + l4][c0];
                bfr[nt][1] = Bs[ks + l4 + 4][c0];
            }
#pragma unroll
            for (int mt = 0; mt < 2; mt++)
#pragma unroll
                for (int nt = 0; nt < 4; nt++)
                    mma_tf32(acc[mt][nt], a[mt][0], a[mt][1], a[mt][2], a[mt][3],
                             bfr[nt][0], bfr[nt][1]);
        }
    }
    __syncthreads();

    // Epilogue 3: u = relu(+xb1), store into Ms
#pragma unroll
    for (int nt = 0; nt < 4; nt++) {
        int c = C0 + nt * 8 + 2 * l4;
        float bx = xb1[c], by = xb1[c + 1];
#pragma unroll
        for (int mt = 0; mt < 2; mt++) {
            int rA = R0 + mt * 16 + qd;
            Ms[rA][c]     = fmaxf(acc[mt][nt].x + bx, 0.f);
            Ms[rA][c + 1] = fmaxf(acc[mt][nt].y + by, 0.f);
            Ms[rA + 8][c]     = fmaxf(acc[mt][nt].z + bx, 0.f);
            Ms[rA + 8][c + 1] = fmaxf(acc[mt][nt].w + by, 0.f);
        }
    }
    __syncthreads();

    // xg + dx atomics
    {
        float4 xw4 = *(const float4*)&xw2[lane * 4];
        float xb2v = xb2[0];
#pragma unroll
        for (int i = 0; i < 8; i++) {
            int r = w * 8 + i;
            float4 uv = *(const float4*)&Ms[r][lane * 4];
            float p = uv.x * xw4.x + uv.y * xw4.y + uv.z * xw4.z + uv.w * xw4.w;
#pragma unroll
            for (int off = 16; off; off >>= 1) p += __shfl_xor_sync(0xFFFFFFFFu, p, off);
            if (lane == 0) {
                float xg = p + xb2v;
                int d = sdst[r];
                atomicAdd(&g_dx[(size_t)d * 3 + 0], srel[r][0] * xg);
                atomicAdd(&g_dx[(size_t)d * 3 + 1], srel[r][1] * xg);
                atomicAdd(&g_dx[(size_t)d * 3 + 2], srel[r][2] * xg);
            }
        }
    }
}

// ---------------------------------------------------------------------------
// Node: out = relu([mi|h]@nw1+nb1)@nw2+nb2 ; x_new = x + dx/E   (fp32 FFMA)
__global__ __launch_bounds__(256) void node_kernel(
    const float* __restrict__ h, const float* __restrict__ x,
    const float* __restrict__ nw1, const float* __restrict__ nb1,
    const float* __restrict__ nw2, const float* __restrict__ nb2,
    float* __restrict__ out)
{
    __shared__ float As[64][17];
    __shared__ float Bs[16][128];
    __shared__ float Ys[64][129];

    const int tid = threadIdx.x;
    const int tx = tid & 31, ty = tid >> 5;
    const int nbase = blockIdx.x * 64;

    float acc[8][4];
#pragma unroll
    for (int i = 0; i < 8; i++)
#pragma unroll
        for (int j = 0; j < 4; j++) acc[i][j] = 0.0f;

    for (int kt = 0; kt < 16; kt++) {
        const int k0 = kt * 16;
#pragma unroll
        for (int l = 0; l < 4; l++) {
            int idx = tid + l * 256;
            int r = idx >> 4, c = idx & 15;
            int n = nbase + r, cg = k0 + c;
            float v = 0.0f;
            if (n < Nn) {
                if (cg < Hh) v = g_mi[(size_t)n * Hh + cg];
                else         v = h[(size_t)n * Hh + (cg - Hh)];
            }
            As[r][c] = v;
        }
#pragma unroll
        for (int l = 0; l < 8; l++) {
            int idx = tid + l * 256;
            int kr = idx >> 7, cc = idx & 127;
            Bs[kr][cc] = nw1[(size_t)(k0 + kr) * Hh + cc];
        }
        __syncthreads();
#pragma unroll
        for (int kk = 0; kk < 16; kk++) {
            float4 b = *(const float4*)&Bs[kk][tx * 4];
#pragma unroll
            for (int i = 0; i < 8; i++) {
                float a = As[ty + 8 * i][kk];
                acc[i][0] += a * b.x; acc[i][1] += a * b.y;
                acc[i][2] += a * b.z; acc[i][3] += a * b.w;
            }
        }
        __syncthreads();
    }

    float4 bb = *(const float4*)&nb1[tx * 4];
#pragma unroll
    for (int i = 0; i < 8; i++) {
        int r = ty + 8 * i;
        Ys[r][tx * 4 + 0] = fmaxf(acc[i][0] + bb.x, 0.0f);
        Ys[r][tx * 4 + 1] = fmaxf(acc[i][1] + bb.y, 0.0f);
        Ys[r][tx * 4 + 2] = fmaxf(acc[i][2] + bb.z, 0.0f);
        Ys[r][tx * 4 + 3] = fmaxf(acc[i][3] + bb.w, 0.0f);
    }
    __syncthreads();

    float acc2[8][4];
#pragma unroll
    for (int i = 0; i < 8; i++)
#pragma unroll
        for (int j = 0; j < 4; j++) acc2[i][j] = 0.0f;

    for (int kt = 0; kt < 8; kt++) {
        const int k0 = kt * 16;
#pragma unroll
        for (int l = 0; l < 8; l++) {
            int idx = tid + l * 256;
            int kr = idx >> 7, cc = idx & 127;
            Bs[kr][cc] = nw2[(size_t)(k0 + kr) * Hh + cc];
        }
        __syncthreads();
#pragma unroll
        for (int kk = 0; kk < 16; kk++) {
            float4 b = *(const float4*)&Bs[kk][tx * 4];
#pragma unroll
            for (int i = 0; i < 8; i++) {
                float a = Ys[ty + 8 * i][k0 + kk];
                acc2[i][0] += a * b.x; acc2[i][1] += a * b.y;
                acc2[i][2] += a * b.z; acc2[i][3] += a * b.w;
            }
        }
        __syncthreads();
    }

    float4 b2v = *(const float4*)&nb2[tx * 4];
#pragma unroll
    for (int i = 0; i < 8; i++) {
        int n = nbase + ty + 8 * i;
        if (n < Nn) {
            float4 o;
            o.x = acc2[i][0] + b2v.x;
            o.y = acc2[i][1] + b2v.y;
            o.z = acc2[i][2] + b2v.z;
            o.w = acc2[i][3] + b2v.w;
            *(float4*)&out[(size_t)n * Hh + tx * 4] = o;
        }
    }

    if (tid < 192) {
        int nl = tid / 3, c = tid % 3;
        int n = nbase + nl;
        if (n < Nn) {
            out[(size_t)Nn * Hh + (size_t)n * 3 + c] =
                x[(size_t)n * 3 + c] + g_dx[(size_t)n * 3 + c] * (1.0f / (float)Ee);
        }
    }
}

// ---------------------------------------------------------------------------
extern "C" void kernel_launch(void* const* d_in, const int* in_sizes, int n_in,
                              void* d_out, int out_size) {
    const float* h    = (const float*)d_in[0];
    const float* x    = (const float*)d_in[1];
    const float* ea   = (const float*)d_in[2];
    const float* ew1  = (const float*)d_in[3];
    const float* eb1  = (const float*)d_in[4];
    const float* ew2  = (const float*)d_in[5];
    const float* eb2  = (const float*)d_in[6];
    const float* infw = (const float*)d_in[7];
    const float* infb = (const float*)d_in[8];
    const float* nw1  = (const float*)d_in[9];
    const float* nb1  = (const float*)d_in[10];
    const float* nw2  = (const float*)d_in[11];
    const float* nb2  = (const float*)d_in[12];
    const float* xw1  = (const float*)d_in[13];
    const float* xb1  = (const float*)d_in[14];
    const float* xw2  = (const float*)d_in[15];
    const float* xb2  = (const float*)d_in[16];
    const int*   eidx = (const int*)d_in[17];
    float* out = (float*)d_out;

    zero_kernel<<<(Nn * Hh + 255) / 256, 256>>>();
    edge_kernel<<<Ee / 64, 256>>>(h, x, ea, ew1, eb1, ew2, eb2,
                                  infw, infb, xw1, xb1, xw2, xb2, eidx);
    node_kernel<<<(Nn + 63) / 64, 256>>>(h, x, nw1, nb1, nw2, nb2, out);
}

// round 3
// speedup vs baseline: 2.9591x; 1.4055x over previous
#include <cuda_runtime.h>
#include <math.h>
#include <stdint.h>

#define Nn 20000
#define Ee 320000
#define Hh 128
#define EFK 28     // edge_attr feature count (EF + K)
#define DIN 304    // 28 + 20 + 128 + 128

// Scratch (static device globals — no runtime allocation)
__device__ float g_mi[(size_t)Nn * Hh];   // segment_sum(mij*eij)
__device__ float g_dx[(size_t)Nn * 3];    // segment_sum(rel_x*xg)
__device__ unsigned g_w1t[DIN * Hh];      // tf32-converted weights
__device__ unsigned g_w2t[Hh * Hh];
__device__ unsigned g_xw1t[Hh * Hh];

// ---------------------------------------------------------------------------
__device__ __forceinline__ unsigned f2tf(float f) {
    unsigned u;
    asm("cvt.rna.tf32.f32 %0, %1;" : "=r"(u) : "f"(f));
    return u;
}

__device__ __forceinline__ void mma_tf32(float4& d,
    unsigned a0, unsigned a1, unsigned a2, unsigned a3,
    unsigned b0, unsigned b1)
{
    asm volatile(
        "mma.sync.aligned.m16n8k8.row.col.f32.tf32.tf32.f32 "
        "{%0,%1,%2,%3}, {%4,%5,%6,%7}, {%8,%9}, {%0,%1,%2,%3};\n"
        : "+f"(d.x), "+f"(d.y), "+f"(d.z), "+f"(d.w)
        : "r"(a0), "r"(a1), "r"(a2), "r"(a3), "r"(b0), "r"(b1));
}

__device__ __forceinline__ void red_add_v4(float* addr, float4 v) {
    asm volatile("red.global.add.v4.f32 [%0], {%1,%2,%3,%4};"
                 :: "l"(addr), "f"(v.x), "f"(v.y), "f"(v.z), "f"(v.w)
                 : "memory");
}

__device__ __forceinline__ void cp16(void* smem, const void* g) {
    unsigned s = (unsigned)__cvta_generic_to_shared(smem);
    asm volatile("cp.async.cg.shared.global [%0], [%1], 16;" :: "r"(s), "l"(g));
}
__device__ __forceinline__ void cp_commit() {
    asm volatile("cp.async.commit_group;" ::: "memory");
}
template<int N> __device__ __forceinline__ void cp_wait() {
    asm volatile("cp.async.wait_group %0;" :: "n"(N) : "memory");
}

// ---------------------------------------------------------------------------
// Prep: zero accumulators + convert edge weights to tf32 (once per call)
__global__ __launch_bounds__(256) void prep_kernel(
    const float* __restrict__ w1, const float* __restrict__ w2,
    const float* __restrict__ xw1)
{
    int i = blockIdx.x * blockDim.x + threadIdx.x;
    if (i < Nn * Hh) g_mi[i] = 0.0f;
    if (i < Nn * 3)  g_dx[i] = 0.0f;
    if (i < DIN * Hh) g_w1t[i] = f2tf(w1[i]);
    if (i < Hh * Hh) {
        g_w2t[i]  = f2tf(w2[i]);
        g_xw1t[i] = f2tf(xw1[i]);
    }
}

// ---------------------------------------------------------------------------
// Fused edge kernel, 128 edges x 128 cols per block, 8 warps (2M x 4N),
// tf32 mma, cp.async 3-stage B pipeline, double-buffered A.
// Dynamic smem layout (bytes):
//   [0,67584)       Ms[128][132] float   (staging t1->mij->u; A dbl-buf aliases front)
//   [67584,93696)   Bs[3][16][136] uint
//   [93696,94208)   sdst[128]
//   [94208,94720)   ssrc[128]
//   [94720,96256)   srel[128][3]
//   [96256,96768)   sl2[128]
#define EDGE_SMEM 96768

__global__ __launch_bounds__(256, 2) void edge_kernel(
    const float* __restrict__ h, const float* __restrict__ x,
    const float* __restrict__ ea,
    const float* __restrict__ b1, const float* __restrict__ b2,
    const float* __restrict__ infw, const float* __restrict__ infb,
    const float* __restrict__ xb1,
    const float* __restrict__ xw2, const float* __restrict__ xb2,
    const int* __restrict__ eidx)
{
    extern __shared__ char sm[];
    float (*Ms)[132]          = (float(*)[132])sm;
    unsigned (*Bs)[16][136]   = (unsigned(*)[16][136])(sm + 67584);
    int*   sdst               = (int*)(sm + 93696);
    int*   ssrc               = (int*)(sm + 94208);
    float (*srel)[3]          = (float(*)[3])(sm + 94720);
    float* sl2                = (float*)(sm + 96256);
    unsigned (*As)[128][20]   = (unsigned(*)[128][20])sm;   // 2 bufs, 20.5KB, alias Ms

    const int tid  = threadIdx.x;
    const int w    = tid >> 5;
    const int lane = tid & 31;
    const int qd   = lane >> 2;
    const int l4   = lane & 3;
    const int R0   = (w >> 2) * 64;     // 0 or 64
    const int C0   = (w & 3) * 32;      // 0,32,64,96
    const int ebase = blockIdx.x * 128;

    if (tid < 128) {
        int e = ebase + tid;
        int d = eidx[e], s = eidx[Ee + e];
        sdst[tid] = d; ssrc[tid] = s;
        float rx = x[d * 3 + 0] - x[s * 3 + 0];
        float ry = x[d * 3 + 1] - x[s * 3 + 1];
        float rz = x[d * 3 + 2] - x[s * 3 + 2];
        srel[tid][0] = rx; srel[tid][1] = ry; srel[tid][2] = rz;
        sl2[tid] = sqrtf(rx * rx + ry * ry + rz * rz);
    }
    __syncthreads();

    const float delta = 100.0f / 19.0f;
    const float coeff = -0.5f / (delta * delta);

    // ---- A-fill lambda-ish macros ----
#define FILL_A_SCALAR(buf, t)                                                   \
    {                                                                           \
        const int kb = (t) * 16;                                                \
        _Pragma("unroll")                                                       \
        for (int l = 0; l < 8; l++) {                                           \
            int idx = tid + l * 256;                                            \
            int r = idx >> 4, c = idx & 15;                                     \
            int cg = kb + c;                                                    \
            float v;                                                            \
            if (cg < EFK) v = ea[(size_t)(ebase + r) * EFK + cg];               \
            else { int j = cg - EFK; float tt = sl2[r] - (float)j * delta;      \
                   v = expf(coeff * tt * tt); }                                 \
            As[buf][r][c] = f2tf(v);                                            \
        }                                                                       \
    }

#define FILL_A_H(buf, t)                                                        \
    {                                                                           \
        const int* ridx = ((t) < 11) ? sdst : ssrc;                             \
        const int hbase = (((t) - 3) & 7) * 16;                                 \
        _Pragma("unroll")                                                       \
        for (int l = 0; l < 2; l++) {                                           \
            int f4 = tid + l * 256;                                             \
            int r = f4 >> 2, c4 = (f4 & 3) * 4;                                 \
            float4 hv = *(const float4*)&h[(size_t)ridx[r] * Hh + hbase + c4];  \
            *(uint4*)&As[buf][r][c4] =                                          \
                make_uint4(f2tf(hv.x), f2tf(hv.y), f2tf(hv.z), f2tf(hv.w));     \
        }                                                                       \
    }

#define ISSUE_B(wsrc, bbuf, t)                                                  \
    {                                                                           \
        _Pragma("unroll")                                                       \
        for (int l = 0; l < 2; l++) {                                           \
            int chunk = tid + l * 256;                                          \
            int kr = chunk >> 5, cc16 = chunk & 31;                             \
            cp16(&Bs[bbuf][kr][cc16 * 4], (wsrc) + ((t) * 16 + kr) * Hh + cc16 * 4); \
        }                                                                       \
        cp_commit();                                                            \
    }

    float4 acc[4][4];
#pragma unroll
    for (int mt = 0; mt < 4; mt++)
#pragma unroll
        for (int nt = 0; nt < 4; nt++) acc[mt][nt] = make_float4(0.f, 0.f, 0.f, 0.f);

#define COMPUTE_TILE(Abuf, bbuf, AEXPR)                                         \
    {                                                                           \
        _Pragma("unroll")                                                       \
        for (int ks = 0; ks < 16; ks += 8) {                                    \
            unsigned a[4][4], bfr[4][2];                                        \
            _Pragma("unroll")                                                   \
            for (int mt = 0; mt < 4; mt++) {                                    \
                int r0 = R0 + mt * 16;                                          \
                a[mt][0] = AEXPR(r0 + qd, ks + l4);                             \
                a[mt][1] = AEXPR(r0 + qd + 8, ks + l4);                         \
                a[mt][2] = AEXPR(r0 + qd, ks + l4 + 4);                         \
                a[mt][3] = AEXPR(r0 + qd + 8, ks + l4 + 4);                     \
            }                                                                   \
            _Pragma("unroll")                                                   \
            for (int nt = 0; nt < 4; nt++) {                                    \
                int c0 = C0 + nt * 8 + qd;                                      \
                bfr[nt][0] = Bs[bbuf][ks + l4][c0];                             \
                bfr[nt][1] = Bs[bbuf][ks + l4 + 4][c0];                         \
            }                                                                   \
            _Pragma("unroll")                                                   \
            for (int mt = 0; mt < 4; mt++)                                      \
                _Pragma("unroll")                                               \
                for (int nt = 0; nt < 4; nt++)                                  \
                    mma_tf32(acc[mt][nt], a[mt][0], a[mt][1], a[mt][2], a[mt][3],\
                             bfr[nt][0], bfr[nt][1]);                           \
        }                                                                       \
    }

#define A_G1(r, c) As[abuf][r][c]
#define A_G2(r, c) __float_as_uint(Ms[r][kbase + (c)])
#define A_G3(r, c) f2tf(Ms[r][kbase + (c)])

    // ================= GEMM1: feat(128x304) @ w1 =================
    FILL_A_SCALAR(0, 0);
    ISSUE_B(g_w1t, 0, 0);
    ISSUE_B(g_w1t, 1, 1);

    for (int kt = 0; kt < 19; kt++) {
        if (kt < 18) cp_wait<1>(); else cp_wait<0>();
        __syncthreads();
        int knext = kt + 1;
        if (knext < 19) {
            int fb = knext & 1;
            if (knext < 3) { FILL_A_SCALAR(fb, knext); }
            else           { FILL_A_H(fb, knext); }
        }
        if (kt + 2 < 19) { int bb = (kt + 2) % 3; ISSUE_B(g_w1t, bb, kt + 2); }
        const int abuf = kt & 1;
        const int bbuf = kt % 3;
        COMPUTE_TILE(abuf, bbuf, A_G1);
    }
    __syncthreads();

    // prologue for GEMM2 B (overlap with epilogue 1)
    ISSUE_B(g_w2t, 0, 0);
    ISSUE_B(g_w2t, 1, 1);

    // Epilogue 1: t1 = relu(+b1), store tf32 bits into Ms
#pragma unroll
    for (int nt = 0; nt < 4; nt++) {
        int c = C0 + nt * 8 + 2 * l4;
        float bx = b1[c], by = b1[c + 1];
#pragma unroll
        for (int mt = 0; mt < 4; mt++) {
            int rA = R0 + mt * 16 + qd;
            Ms[rA][c]     = __uint_as_float(f2tf(fmaxf(acc[mt][nt].x + bx, 0.f)));
            Ms[rA][c + 1] = __uint_as_float(f2tf(fmaxf(acc[mt][nt].y + by, 0.f)));
            Ms[rA + 8][c]     = __uint_as_float(f2tf(fmaxf(acc[mt][nt].z + bx, 0.f)));
            Ms[rA + 8][c + 1] = __uint_as_float(f2tf(fmaxf(acc[mt][nt].w + by, 0.f)));
        }
    }

    // ================= GEMM2: t1(128x128) @ w2 =================
#pragma unroll
    for (int mt = 0; mt < 4; mt++)
#pragma unroll
        for (int nt = 0; nt < 4; nt++) acc[mt][nt] = make_float4(0.f, 0.f, 0.f, 0.f);

    for (int kt = 0; kt < 8; kt++) {
        if (kt < 7) cp_wait<1>(); else cp_wait<0>();
        __syncthreads();
        if (kt + 2 < 8) { int bb = (kt + 2) % 3; ISSUE_B(g_w2t, bb, kt + 2); }
        const int kbase = kt * 16;
        const int bbuf = kt % 3;
        COMPUTE_TILE(0, bbuf, A_G2);
    }
    __syncthreads();

    // Epilogue 2: mij = relu(+b2), fp32 into Ms
#pragma unroll
    for (int nt = 0; nt < 4; nt++) {
        int c = C0 + nt * 8 + 2 * l4;
        float bx = b2[c], by = b2[c + 1];
#pragma unroll
        for (int mt = 0; mt < 4; mt++) {
            int rA = R0 + mt * 16 + qd;
            Ms[rA][c]     = fmaxf(acc[mt][nt].x + bx, 0.f);
            Ms[rA][c + 1] = fmaxf(acc[mt][nt].y + by, 0.f);
            Ms[rA + 8][c]     = fmaxf(acc[mt][nt].z + bx, 0.f);
            Ms[rA + 8][c + 1] = fmaxf(acc[mt][nt].w + by, 0.f);
        }
    }
    // prologue for GEMM3 B (overlaps eij/atomics)
    ISSUE_B(g_xw1t, 0, 0);
    ISSUE_B(g_xw1t, 1, 1);
    __syncthreads();

    // eij + mi atomics: warp w handles rows w*16 .. w*16+15
    {
        float4 iw4 = *(const float4*)&infw[lane * 4];
        float ib = infb[0];
#pragma unroll
        for (int i = 0; i < 16; i++) {
            int r = w * 16 + i;
            float4 mv = *(const float4*)&Ms[r][lane * 4];
            float p = mv.x * iw4.x + mv.y * iw4.y + mv.z * iw4.z + mv.w * iw4.w;
#pragma unroll
            for (int off = 16; off; off >>= 1) p += __shfl_xor_sync(0xFFFFFFFFu, p, off);
            float eij = 1.0f / (1.0f + expf(-(p + ib)));
            int d = sdst[r];
            red_add_v4(&g_mi[(size_t)d * Hh + lane * 4],
                       make_float4(mv.x * eij, mv.y * eij, mv.z * eij, mv.w * eij));
        }
    }

    // ================= GEMM3: mij(128x128) @ xw1 =================
#pragma unroll
    for (int mt = 0; mt < 4; mt++)
#pragma unroll
        for (int nt = 0; nt < 4; nt++) acc[mt][nt] = make_float4(0.f, 0.f, 0.f, 0.f);

    for (int kt = 0; kt < 8; kt++) {
        if (kt < 7) cp_wait<1>(); else cp_wait<0>();
        __syncthreads();
        if (kt + 2 < 8) { int bb = (kt + 2) % 3; ISSUE_B(g_xw1t, bb, kt + 2); }
        const int kbase = kt * 16;
        const int bbuf = kt % 3;
        COMPUTE_TILE(0, bbuf, A_G3);
    }
    __syncthreads();

    // Epilogue 3: u = relu(+xb1) into Ms
#pragma unroll
    for (int nt = 0; nt < 4; nt++) {
        int c = C0 + nt * 8 + 2 * l4;
        float bx = xb1[c], by = xb1[c + 1];
#pragma unroll
        for (int mt = 0; mt < 4; mt++) {
            int rA = R0 + mt * 16 + qd;
            Ms[rA][c]     = fmaxf(acc[mt][nt].x + bx, 0.f);
            Ms[rA][c + 1] = fmaxf(acc[mt][nt].y + by, 0.f);
            Ms[rA + 8][c]     = fmaxf(acc[mt][nt].z + bx, 0.f);
            Ms[rA + 8][c + 1] = fmaxf(acc[mt][nt].w + by, 0.f);
        }
    }
    __syncthreads();

    // xg + dx atomics
    {
        float4 xw4 = *(const float4*)&xw2[lane * 4];
        float xb2v = xb2[0];
#pragma unroll
        for (int i = 0; i < 16; i++) {
            int r = w * 16 + i;
            float4 uv = *(const float4*)&Ms[r][lane * 4];
            float p = uv.x * xw4.x + uv.y * xw4.y + uv.z * xw4.z + uv.w * xw4.w;
#pragma unroll
            for (int off = 16; off; off >>= 1) p += __shfl_xor_sync(0xFFFFFFFFu, p, off);
            if (lane == 0) {
                float xg = p + xb2v;
                int d = sdst[r];
                atomicAdd(&g_dx[(size_t)d * 3 + 0], srel[r][0] * xg);
                atomicAdd(&g_dx[(size_t)d * 3 + 1], srel[r][1] * xg);
                atomicAdd(&g_dx[(size_t)d * 3 + 2], srel[r][2] * xg);
            }
        }
    }
#undef FILL_A_SCALAR
#undef FILL_A_H
#undef ISSUE_B
#undef COMPUTE_TILE
#undef A_G1
#undef A_G2
#undef A_G3
}

// ---------------------------------------------------------------------------
// Node: out = relu([mi|h]@nw1+nb1)@nw2+nb2 ; x_new = x + dx/E   (fp32 FFMA)
__global__ __launch_bounds__(256) void node_kernel(
    const float* __restrict__ h, const float* __restrict__ x,
    const float* __restrict__ nw1, const float* __restrict__ nb1,
    const float* __restrict__ nw2, const float* __restrict__ nb2,
    float* __restrict__ out)
{
    __shared__ float As[64][17];
    __shared__ float Bs[16][128];
    __shared__ float Ys[64][129];

    const int tid = threadIdx.x;
    const int tx = tid & 31, ty = tid >> 5;
    const int nbase = blockIdx.x * 64;

    float acc[8][4];
#pragma unroll
    for (int i = 0; i < 8; i++)
#pragma unroll
        for (int j = 0; j < 4; j++) acc[i][j] = 0.0f;

    for (int kt = 0; kt < 16; kt++) {
        const int k0 = kt * 16;
#pragma unroll
        for (int l = 0; l < 4; l++) {
            int idx = tid + l * 256;
            int r = idx >> 4, c = idx & 15;
            int n = nbase + r, cg = k0 + c;
            float v = 0.0f;
            if (n < Nn) {
                if (cg < Hh) v = g_mi[(size_t)n * Hh + cg];
                else         v = h[(size_t)n * Hh + (cg - Hh)];
            }
            As[r][c] = v;
        }
#pragma unroll
        for (int l = 0; l < 8; l++) {
            int idx = tid + l * 256;
            int kr = idx >> 7, cc = idx & 127;
            Bs[kr][cc] = nw1[(size_t)(k0 + kr) * Hh + cc];
        }
        __syncthreads();
#pragma unroll
        for (int kk = 0; kk < 16; kk++) {
            float4 b = *(const float4*)&Bs[kk][tx * 4];
#pragma unroll
            for (int i = 0; i < 8; i++) {
                float a = As[ty + 8 * i][kk];
                acc[i][0] += a * b.x; acc[i][1] += a * b.y;
                acc[i][2] += a * b.z; acc[i][3] += a * b.w;
            }
        }
        __syncthreads();
    }

    float4 bb = *(const float4*)&nb1[tx * 4];
#pragma unroll
    for (int i = 0; i < 8; i++) {
        int r = ty + 8 * i;
        Ys[r][tx * 4 + 0] = fmaxf(acc[i][0] + bb.x, 0.0f);
        Ys[r][tx * 4 + 1] = fmaxf(acc[i][1] + bb.y, 0.0f);
        Ys[r][tx * 4 + 2] = fmaxf(acc[i][2] + bb.z, 0.0f);
        Ys[r][tx * 4 + 3] = fmaxf(acc[i][3] + bb.w, 0.0f);
    }
    __syncthreads();

    float acc2[8][4];
#pragma unroll
    for (int i = 0; i < 8; i++)
#pragma unroll
        for (int j = 0; j < 4; j++) acc2[i][j] = 0.0f;

    for (int kt = 0; kt < 8; kt++) {
        const int k0 = kt * 16;
#pragma unroll
        for (int l = 0; l < 8; l++) {
            int idx = tid + l * 256;
            int kr = idx >> 7, cc = idx & 127;
            Bs[kr][cc] = nw2[(size_t)(k0 + kr) * Hh + cc];
        }
        __syncthreads();
#pragma unroll
        for (int kk = 0; kk < 16; kk++) {
            float4 b = *(const float4*)&Bs[kk][tx * 4];
#pragma unroll
            for (int i = 0; i < 8; i++) {
                float a = Ys[ty + 8 * i][k0 + kk];
                acc2[i][0] += a * b.x; acc2[i][1] += a * b.y;
                acc2[i][2] += a * b.z; acc2[i][3] += a * b.w;
            }
        }
        __syncthreads();
    }

    float4 b2v = *(const float4*)&nb2[tx * 4];
#pragma unroll
    for (int i = 0; i < 8; i++) {
        int n = nbase + ty + 8 * i;
        if (n < Nn) {
            float4 o;
            o.x = acc2[i][0] + b2v.x;
            o.y = acc2[i][1] + b2v.y;
            o.z = acc2[i][2] + b2v.z;
            o.w = acc2[i][3] + b2v.w;
            *(float4*)&out[(size_t)n * Hh + tx * 4] = o;
        }
    }

    if (tid < 192) {
        int nl = tid / 3, c = tid % 3;
        int n = nbase + nl;
        if (n < Nn) {
            out[(size_t)Nn * Hh + (size_t)n * 3 + c] =
                x[(size_t)n * 3 + c] + g_dx[(size_t)n * 3 + c] * (1.0f / (float)Ee);
        }
    }
}

// ---------------------------------------------------------------------------
extern "C" void kernel_launch(void* const* d_in, const int* in_sizes, int n_in,
                              void* d_out, int out_size) {
    const float* h    = (const float*)d_in[0];
    const float* x    = (const float*)d_in[1];
    const float* ea   = (const float*)d_in[2];
    const float* ew1  = (const float*)d_in[3];
    const float* eb1  = (const float*)d_in[4];
    const float* ew2  = (const float*)d_in[5];
    const float* eb2  = (const float*)d_in[6];
    const float* infw = (const float*)d_in[7];
    const float* infb = (const float*)d_in[8];
    const float* nw1  = (const float*)d_in[9];
    const float* nb1  = (const float*)d_in[10];
    const float* nw2  = (const float*)d_in[11];
    const float* nb2  = (const float*)d_in[12];
    const float* xw1  = (const float*)d_in[13];
    const float* xb1  = (const float*)d_in[14];
    const float* xw2  = (const float*)d_in[15];
    const float* xb2  = (const float*)d_in[16];
    const int*   eidx = (const int*)d_in[17];
    float* out = (float*)d_out;

    cudaFuncSetAttribute(edge_kernel,
                         cudaFuncAttributeMaxDynamicSharedMemorySize, EDGE_SMEM);

    prep_kernel<<<(Nn * Hh + 255) / 256, 256>>>(ew1, ew2, xw1);
    edge_kernel<<<Ee / 128, 256, EDGE_SMEM>>>(h, x, ea, eb1, eb2,
                                              infw, infb, xb1, xw2, xb2, eidx);
    node_kernel<<<(Nn + 63) / 64, 256>>>(h, x, nw1, nb1, nw2, nb2, out);
}

// round 4
// speedup vs baseline: 3.3112x; 1.1190x over previous
#include <cuda_runtime.h>
#include <math.h>
#include <stdint.h>

#define Nn 20000
#define Ee 320000
#define Hh 128
#define EFK 28     // edge_attr feature count (EF + K)
#define DIN 304    // 28 + 20 + 128 + 128

// Scratch (static device globals — no runtime allocation)
__device__ float g_mi[(size_t)Nn * Hh];   // segment_sum(mij*eij)
__device__ float g_dx[(size_t)Nn * 3];    // segment_sum(rel_x*xg)
__device__ unsigned g_w1t[DIN * Hh];      // tf32-converted weights
__device__ unsigned g_w2t[Hh * Hh];
__device__ unsigned g_xw1t[Hh * Hh];
__device__ unsigned g_nw1t[2 * Hh * Hh];
__device__ unsigned g_nw2t[Hh * Hh];

// ---------------------------------------------------------------------------
__device__ __forceinline__ unsigned f2tf(float f) {
    unsigned u;
    asm("cvt.rna.tf32.f32 %0, %1;" : "=r"(u) : "f"(f));
    return u;
}

__device__ __forceinline__ void mma_tf32(float4& d,
    unsigned a0, unsigned a1, unsigned a2, unsigned a3,
    unsigned b0, unsigned b1)
{
    asm volatile(
        "mma.sync.aligned.m16n8k8.row.col.f32.tf32.tf32.f32 "
        "{%0,%1,%2,%3}, {%4,%5,%6,%7}, {%8,%9}, {%0,%1,%2,%3};\n"
        : "+f"(d.x), "+f"(d.y), "+f"(d.z), "+f"(d.w)
        : "r"(a0), "r"(a1), "r"(a2), "r"(a3), "r"(b0), "r"(b1));
}

__device__ __forceinline__ void red_add_v4(float* addr, float4 v) {
    asm volatile("red.global.add.v4.f32 [%0], {%1,%2,%3,%4};"
                 :: "l"(addr), "f"(v.x), "f"(v.y), "f"(v.z), "f"(v.w)
                 : "memory");
}

__device__ __forceinline__ void cp16(void* smem, const void* g) {
    unsigned s = (unsigned)__cvta_generic_to_shared(smem);
    asm volatile("cp.async.cg.shared.global [%0], [%1], 16;" :: "r"(s), "l"(g));
}
__device__ __forceinline__ void cp_commit() {
    asm volatile("cp.async.commit_group;" ::: "memory");
}
template<int N> __device__ __forceinline__ void cp_wait() {
    asm volatile("cp.async.wait_group %0;" :: "n"(N) : "memory");
}

// ---------------------------------------------------------------------------
// Prep: zero accumulators + convert all weights to tf32 (once per call)
__global__ __launch_bounds__(256) void prep_kernel(
    const float* __restrict__ w1, const float* __restrict__ w2,
    const float* __restrict__ xw1,
    const float* __restrict__ nw1, const float* __restrict__ nw2)
{
    int i = blockIdx.x * blockDim.x + threadIdx.x;
    if (i < Nn * Hh) g_mi[i] = 0.0f;
    if (i < Nn * 3)  g_dx[i] = 0.0f;
    if (i < DIN * Hh) g_w1t[i] = f2tf(w1[i]);
    if (i < 2 * Hh * Hh) g_nw1t[i] = f2tf(nw1[i]);
    if (i < Hh * Hh) {
        g_w2t[i]  = f2tf(w2[i]);
        g_xw1t[i] = f2tf(xw1[i]);
        g_nw2t[i] = f2tf(nw2[i]);
    }
}

// ---------------------------------------------------------------------------
// Shared smem layout for edge & node kernels (dynamic):
//   [0,67584)       Ms[128][132] float   (staging; A dbl-buf aliases front)
//   [67584,93696)   Bs[3][16][136] uint
//   edge extra:
//   [93696,94208)   sdst[128]
//   [94208,94720)   ssrc[128]
//   [94720,96256)   srel[128][3]
//   [96256,96768)   sl2[128]
#define EDGE_SMEM 96768
#define NODE_SMEM 93696

// ---------------------------------------------------------------------------
__global__ __launch_bounds__(256, 2) void edge_kernel(
    const float* __restrict__ h, const float* __restrict__ x,
    const float* __restrict__ ea,
    const float* __restrict__ b1, const float* __restrict__ b2,
    const float* __restrict__ infw, const float* __restrict__ infb,
    const float* __restrict__ xb1,
    const float* __restrict__ xw2, const float* __restrict__ xb2,
    const int* __restrict__ eidx)
{
    extern __shared__ char sm[];
    float (*Ms)[132]          = (float(*)[132])sm;
    unsigned (*Bs)[16][136]   = (unsigned(*)[16][136])(sm + 67584);
    int*   sdst               = (int*)(sm + 93696);
    int*   ssrc               = (int*)(sm + 94208);
    float (*srel)[3]          = (float(*)[3])(sm + 94720);
    float* sl2                = (float*)(sm + 96256);
    unsigned (*As)[128][20]   = (unsigned(*)[128][20])sm;   // 2 bufs alias Ms

    const int tid  = threadIdx.x;
    const int w    = tid >> 5;
    const int lane = tid & 31;
    const int qd   = lane >> 2;
    const int l4   = lane & 3;
    const int R0   = (w >> 2) * 64;
    const int C0   = (w & 3) * 32;
    const int ebase = blockIdx.x * 128;

    if (tid < 128) {
        int e = ebase + tid;
        int d = eidx[e], s = eidx[Ee + e];
        sdst[tid] = d; ssrc[tid] = s;
        float rx = x[d * 3 + 0] - x[s * 3 + 0];
        float ry = x[d * 3 + 1] - x[s * 3 + 1];
        float rz = x[d * 3 + 2] - x[s * 3 + 2];
        srel[tid][0] = rx; srel[tid][1] = ry; srel[tid][2] = rz;
        sl2[tid] = sqrtf(rx * rx + ry * ry + rz * rz);
    }
    __syncthreads();

    const float delta = 100.0f / 19.0f;
    const float coeff = -0.5f / (delta * delta);

#define FILL_A_SCALAR(buf, t)                                                   \
    {                                                                           \
        const int kb = (t) * 16;                                                \
        _Pragma("unroll")                                                       \
        for (int l = 0; l < 8; l++) {                                           \
            int idx = tid + l * 256;                                            \
            int r = idx >> 4, c = idx & 15;                                     \
            int cg = kb + c;                                                    \
            float v;                                                            \
            if (cg < EFK) v = ea[(size_t)(ebase + r) * EFK + cg];               \
            else { int j = cg - EFK; float tt = sl2[r] - (float)j * delta;      \
                   v = expf(coeff * tt * tt); }                                 \
            As[buf][r][c] = f2tf(v);                                            \
        }                                                                       \
    }

#define FILL_A_H(buf, t)                                                        \
    {                                                                           \
        const int* ridx = ((t) < 11) ? sdst : ssrc;                             \
        const int hbase = (((t) - 3) & 7) * 16;                                 \
        _Pragma("unroll")                                                       \
        for (int l = 0; l < 2; l++) {                                           \
            int f4 = tid + l * 256;                                             \
            int r = f4 >> 2, c4 = (f4 & 3) * 4;                                 \
            float4 hv = *(const float4*)&h[(size_t)ridx[r] * Hh + hbase + c4];  \
            *(uint4*)&As[buf][r][c4] =                                          \
                make_uint4(f2tf(hv.x), f2tf(hv.y), f2tf(hv.z), f2tf(hv.w));     \
        }                                                                       \
    }

#define ISSUE_B(wsrc, bbuf, t)                                                  \
    {                                                                           \
        _Pragma("unroll")                                                       \
        for (int l = 0; l < 2; l++) {                                           \
            int chunk = tid + l * 256;                                          \
            int kr = chunk >> 5, cc16 = chunk & 31;                             \
            cp16(&Bs[bbuf][kr][cc16 * 4], (wsrc) + ((t) * 16 + kr) * Hh + cc16 * 4); \
        }                                                                       \
        cp_commit();                                                            \
    }

    float4 acc[4][4];
#pragma unroll
    for (int mt = 0; mt < 4; mt++)
#pragma unroll
        for (int nt = 0; nt < 4; nt++) acc[mt][nt] = make_float4(0.f, 0.f, 0.f, 0.f);

#define COMPUTE_TILE(Abuf, bbuf, AEXPR)                                         \
    {                                                                           \
        _Pragma("unroll")                                                       \
        for (int ks = 0; ks < 16; ks += 8) {                                    \
            unsigned a[4][4], bfr[4][2];                                        \
            _Pragma("unroll")                                                   \
            for (int mt = 0; mt < 4; mt++) {                                    \
                int r0 = R0 + mt * 16;                                          \
                a[mt][0] = AEXPR(r0 + qd, ks + l4);                             \
                a[mt][1] = AEXPR(r0 + qd + 8, ks + l4);                         \
                a[mt][2] = AEXPR(r0 + qd, ks + l4 + 4);                         \
                a[mt][3] = AEXPR(r0 + qd + 8, ks + l4 + 4);                     \
            }                                                                   \
            _Pragma("unroll")                                                   \
            for (int nt = 0; nt < 4; nt++) {                                    \
                int c0 = C0 + nt * 8 + qd;                                      \
                bfr[nt][0] = Bs[bbuf][ks + l4][c0];                             \
                bfr[nt][1] = Bs[bbuf][ks + l4 + 4][c0];                         \
            }                                                                   \
            _Pragma("unroll")                                                   \
            for (int mt = 0; mt < 4; mt++)                                      \
                _Pragma("unroll")                                               \
                for (int nt = 0; nt < 4; nt++)                                  \
                    mma_tf32(acc[mt][nt], a[mt][0], a[mt][1], a[mt][2], a[mt][3],\
                             bfr[nt][0], bfr[nt][1]);                           \
        }                                                                       \
    }

#define A_G1(r, c) As[abuf][r][c]
#define A_RAW(r, c) __float_as_uint(Ms[r][kbase + (c)])

    // ================= GEMM1: feat(128x304) @ w1 =================
    FILL_A_SCALAR(0, 0);
    ISSUE_B(g_w1t, 0, 0);
    ISSUE_B(g_w1t, 1, 1);

    for (int kt = 0; kt < 19; kt++) {
        if (kt < 18) cp_wait<1>(); else cp_wait<0>();
        __syncthreads();
        int knext = kt + 1;
        if (knext < 19) {
            int fb = knext & 1;
            if (knext < 3) { FILL_A_SCALAR(fb, knext); }
            else           { FILL_A_H(fb, knext); }
        }
        if (kt + 2 < 19) { int bb = (kt + 2) % 3; ISSUE_B(g_w1t, bb, kt + 2); }
        const int abuf = kt & 1;
        const int bbuf = kt % 3;
        COMPUTE_TILE(abuf, bbuf, A_G1);
    }
    __syncthreads();

    ISSUE_B(g_w2t, 0, 0);
    ISSUE_B(g_w2t, 1, 1);

    // Epilogue 1: t1 = relu(+b1) as tf32 bits
#pragma unroll
    for (int nt = 0; nt < 4; nt++) {
        int c = C0 + nt * 8 + 2 * l4;
        float bx = b1[c], by = b1[c + 1];
#pragma unroll
        for (int mt = 0; mt < 4; mt++) {
            int rA = R0 + mt * 16 + qd;
            Ms[rA][c]     = __uint_as_float(f2tf(fmaxf(acc[mt][nt].x + bx, 0.f)));
            Ms[rA][c + 1] = __uint_as_float(f2tf(fmaxf(acc[mt][nt].y + by, 0.f)));
            Ms[rA + 8][c]     = __uint_as_float(f2tf(fmaxf(acc[mt][nt].z + bx, 0.f)));
            Ms[rA + 8][c + 1] = __uint_as_float(f2tf(fmaxf(acc[mt][nt].w + by, 0.f)));
        }
    }

    // ================= GEMM2: t1(128x128) @ w2 =================
#pragma unroll
    for (int mt = 0; mt < 4; mt++)
#pragma unroll
        for (int nt = 0; nt < 4; nt++) acc[mt][nt] = make_float4(0.f, 0.f, 0.f, 0.f);

    for (int kt = 0; kt < 8; kt++) {
        if (kt < 7) cp_wait<1>(); else cp_wait<0>();
        __syncthreads();
        if (kt + 2 < 8) { int bb = (kt + 2) % 3; ISSUE_B(g_w2t, bb, kt + 2); }
        const int kbase = kt * 16;
        const int bbuf = kt % 3;
        COMPUTE_TILE(0, bbuf, A_RAW);
    }
    __syncthreads();

    // Epilogue 2: mij = relu(+b2), fp32 into Ms
#pragma unroll
    for (int nt = 0; nt < 4; nt++) {
        int c = C0 + nt * 8 + 2 * l4;
        float bx = b2[c], by = b2[c + 1];
#pragma unroll
        for (int mt = 0; mt < 4; mt++) {
            int rA = R0 + mt * 16 + qd;
            Ms[rA][c]     = fmaxf(acc[mt][nt].x + bx, 0.f);
            Ms[rA][c + 1] = fmaxf(acc[mt][nt].y + by, 0.f);
            Ms[rA + 8][c]     = fmaxf(acc[mt][nt].z + bx, 0.f);
            Ms[rA + 8][c + 1] = fmaxf(acc[mt][nt].w + by, 0.f);
        }
    }
    ISSUE_B(g_xw1t, 0, 0);
    ISSUE_B(g_xw1t, 1, 1);
    __syncthreads();

    // eij + mi atomics; also convert mij rows to tf32 bits in-place for GEMM3
    {
        float4 iw4 = *(const float4*)&infw[lane * 4];
        float ib = infb[0];
#pragma unroll
        for (int i = 0; i < 16; i++) {
            int r = w * 16 + i;
            float4 mv = *(const float4*)&Ms[r][lane * 4];
            float p = mv.x * iw4.x + mv.y * iw4.y + mv.z * iw4.z + mv.w * iw4.w;
#pragma unroll
            for (int off = 16; off; off >>= 1) p += __shfl_xor_sync(0xFFFFFFFFu, p, off);
            float eij = 1.0f / (1.0f + expf(-(p + ib)));
            int d = sdst[r];
            red_add_v4(&g_mi[(size_t)d * Hh + lane * 4],
                       make_float4(mv.x * eij, mv.y * eij, mv.z * eij, mv.w * eij));
            *(uint4*)&Ms[r][lane * 4] =
                make_uint4(f2tf(mv.x), f2tf(mv.y), f2tf(mv.z), f2tf(mv.w));
        }
    }

    // ================= GEMM3: mij(128x128) @ xw1 =================
#pragma unroll
    for (int mt = 0; mt < 4; mt++)
#pragma unroll
        for (int nt = 0; nt < 4; nt++) acc[mt][nt] = make_float4(0.f, 0.f, 0.f, 0.f);

    for (int kt = 0; kt < 8; kt++) {
        if (kt < 7) cp_wait<1>(); else cp_wait<0>();
        __syncthreads();
        if (kt + 2 < 8) { int bb = (kt + 2) % 3; ISSUE_B(g_xw1t, bb, kt + 2); }
        const int kbase = kt * 16;
        const int bbuf = kt % 3;
        COMPUTE_TILE(0, bbuf, A_RAW);
    }
    __syncthreads();

    // Epilogue 3: u = relu(+xb1) into Ms
#pragma unroll
    for (int nt = 0; nt < 4; nt++) {
        int c = C0 + nt * 8 + 2 * l4;
        float bx = xb1[c], by = xb1[c + 1];
#pragma unroll
        for (int mt = 0; mt < 4; mt++) {
            int rA = R0 + mt * 16 + qd;
            Ms[rA][c]     = fmaxf(acc[mt][nt].x + bx, 0.f);
            Ms[rA][c + 1] = fmaxf(acc[mt][nt].y + by, 0.f);
            Ms[rA + 8][c]     = fmaxf(acc[mt][nt].z + bx, 0.f);
            Ms[rA + 8][c + 1] = fmaxf(acc[mt][nt].w + by, 0.f);
        }
    }
    __syncthreads();

    // xg + dx atomics
    {
        float4 xw4 = *(const float4*)&xw2[lane * 4];
        float xb2v = xb2[0];
#pragma unroll
        for (int i = 0; i < 16; i++) {
            int r = w * 16 + i;
            float4 uv = *(const float4*)&Ms[r][lane * 4];
            float p = uv.x * xw4.x + uv.y * xw4.y + uv.z * xw4.z + uv.w * xw4.w;
#pragma unroll
            for (int off = 16; off; off >>= 1) p += __shfl_xor_sync(0xFFFFFFFFu, p, off);
            if (lane == 0) {
                float xg = p + xb2v;
                int d = sdst[r];
                atomicAdd(&g_dx[(size_t)d * 3 + 0], srel[r][0] * xg);
                atomicAdd(&g_dx[(size_t)d * 3 + 1], srel[r][1] * xg);
                atomicAdd(&g_dx[(size_t)d * 3 + 2], srel[r][2] * xg);
            }
        }
    }
#undef FILL_A_SCALAR
#undef FILL_A_H
}

// ---------------------------------------------------------------------------
// Node (tf32 mma): out = relu([mi|h]@nw1+nb1)@nw2+nb2 ; x_new = x + dx/E
__global__ __launch_bounds__(256, 2) void node_kernel(
    const float* __restrict__ h, const float* __restrict__ x,
    const float* __restrict__ nb1, const float* __restrict__ nb2,
    float* __restrict__ out)
{
    extern __shared__ char sm[];
    float (*Ms)[132]          = (float(*)[132])sm;
    unsigned (*Bs)[16][136]   = (unsigned(*)[16][136])(sm + 67584);
    unsigned (*As)[128][20]   = (unsigned(*)[128][20])sm;

    const int tid  = threadIdx.x;
    const int w    = tid >> 5;
    const int lane = tid & 31;
    const int qd   = lane >> 2;
    const int l4   = lane & 3;
    const int R0   = (w >> 2) * 64;
    const int C0   = (w & 3) * 32;
    const int nbase = blockIdx.x * 128;

#define NFILL(buf, t)                                                           \
    {                                                                           \
        _Pragma("unroll")                                                       \
        for (int l = 0; l < 2; l++) {                                           \
            int f4 = tid + l * 256;                                             \
            int r = f4 >> 2, c4 = (f4 & 3) * 4;                                 \
            int n = nbase + r;                                                  \
            float4 v = make_float4(0.f, 0.f, 0.f, 0.f);                         \
            if (n < Nn) {                                                       \
                if ((t) < 8) v = *(const float4*)&g_mi[(size_t)n * Hh + (t) * 16 + c4]; \
                else         v = *(const float4*)&h[(size_t)n * Hh + ((t) - 8) * 16 + c4]; \
            }                                                                   \
            *(uint4*)&As[buf][r][c4] =                                          \
                make_uint4(f2tf(v.x), f2tf(v.y), f2tf(v.z), f2tf(v.w));         \
        }                                                                       \
    }

    float4 acc[4][4];
#pragma unroll
    for (int mt = 0; mt < 4; mt++)
#pragma unroll
        for (int nt = 0; nt < 4; nt++) acc[mt][nt] = make_float4(0.f, 0.f, 0.f, 0.f);

    // ================= GEMM1: [mi|h](128x256) @ nw1 =================
    NFILL(0, 0);
    ISSUE_B(g_nw1t, 0, 0);
    ISSUE_B(g_nw1t, 1, 1);

    for (int kt = 0; kt < 16; kt++) {
        if (kt < 15) cp_wait<1>(); else cp_wait<0>();
        __syncthreads();
        if (kt + 1 < 16) { NFILL((kt + 1) & 1, kt + 1); }
        if (kt + 2 < 16) { int bb = (kt + 2) % 3; ISSUE_B(g_nw1t, bb, kt + 2); }
        const int abuf = kt & 1;
        const int bbuf = kt % 3;
        COMPUTE_TILE(abuf, bbuf, A_G1);
    }
    __syncthreads();

    ISSUE_B(g_nw2t, 0, 0);
    ISSUE_B(g_nw2t, 1, 1);

    // Epilogue 1: y = relu(+nb1) as tf32 bits into Ms
#pragma unroll
    for (int nt = 0; nt < 4; nt++) {
        int c = C0 + nt * 8 + 2 * l4;
        float bx = nb1[c], by = nb1[c + 1];
#pragma unroll
        for (int mt = 0; mt < 4; mt++) {
            int rA = R0 + mt * 16 + qd;
            Ms[rA][c]     = __uint_as_float(f2tf(fmaxf(acc[mt][nt].x + bx, 0.f)));
            Ms[rA][c + 1] = __uint_as_float(f2tf(fmaxf(acc[mt][nt].y + by, 0.f)));
            Ms[rA + 8][c]     = __uint_as_float(f2tf(fmaxf(acc[mt][nt].z + bx, 0.f)));
            Ms[rA + 8][c + 1] = __uint_as_float(f2tf(fmaxf(acc[mt][nt].w + by, 0.f)));
        }
    }

    // ================= GEMM2: y(128x128) @ nw2 =================
#pragma unroll
    for (int mt = 0; mt < 4; mt++)
#pragma unroll
        for (int nt = 0; nt < 4; nt++) acc[mt][nt] = make_float4(0.f, 0.f, 0.f, 0.f);

    for (int kt = 0; kt < 8; kt++) {
        if (kt < 7) cp_wait<1>(); else cp_wait<0>();
        __syncthreads();
        if (kt + 2 < 8) { int bb = (kt + 2) % 3; ISSUE_B(g_nw2t, bb, kt + 2); }
        const int kbase = kt * 16;
        const int bbuf = kt % 3;
        COMPUTE_TILE(0, bbuf, A_RAW);
    }

    // Epilogue 2: out = acc + nb2 (direct global stores, guarded)
#pragma unroll
    for (int nt = 0; nt < 4; nt++) {
        int c = C0 + nt * 8 + 2 * l4;
        float bx = nb2[c], by = nb2[c + 1];
#pragma unroll
        for (int mt = 0; mt < 4; mt++) {
            int r = R0 + mt * 16 + qd;
            int n = nbase + r;
            if (n < Nn) {
                out[(size_t)n * Hh + c]     = acc[mt][nt].x + bx;
                out[(size_t)n * Hh + c + 1] = acc[mt][nt].y + by;
            }
            int n2 = n + 8;
            if (n2 < Nn) {
                out[(size_t)n2 * Hh + c]     = acc[mt][nt].z + bx;
                out[(size_t)n2 * Hh + c + 1] = acc[mt][nt].w + by;
            }
        }
    }

    // x update
    for (int i = tid; i < 128 * 3; i += 256) {
        int nl = i / 3, c = i % 3;
        int n = nbase + nl;
        if (n < Nn) {
            out[(size_t)Nn * Hh + (size_t)n * 3 + c] =
                x[(size_t)n * 3 + c] + g_dx[(size_t)n * 3 + c] * (1.0f / (float)Ee);
        }
    }
#undef NFILL
#undef ISSUE_B
#undef COMPUTE_TILE
#undef A_G1
#undef A_RAW
}

// ---------------------------------------------------------------------------
extern "C" void kernel_launch(void* const* d_in, const int* in_sizes, int n_in,
                              void* d_out, int out_size) {
    const float* h    = (const float*)d_in[0];
    const float* x    = (const float*)d_in[1];
    const float* ea   = (const float*)d_in[2];
    const float* ew1  = (const float*)d_in[3];
    const float* eb1  = (const float*)d_in[4];
    const float* ew2  = (const float*)d_in[5];
    const float* eb2  = (const float*)d_in[6];
    const float* infw = (const float*)d_in[7];
    const float* infb = (const float*)d_in[8];
    const float* nw1  = (const float*)d_in[9];
    const float* nb1  = (const float*)d_in[10];
    const float* nw2  = (const float*)d_in[11];
    const float* nb2  = (const float*)d_in[12];
    const float* xw1  = (const float*)d_in[13];
    const float* xb1  = (const float*)d_in[14];
    const float* xw2  = (const float*)d_in[15];
    const float* xb2  = (const float*)d_in[16];
    const int*   eidx = (const int*)d_in[17];
    float* out = (float*)d_out;

    cudaFuncSetAttribute(edge_kernel,
                         cudaFuncAttributeMaxDynamicSharedMemorySize, EDGE_SMEM);
    cudaFuncSetAttribute(node_kernel,
                         cudaFuncAttributeMaxDynamicSharedMemorySize, NODE_SMEM);

    prep_kernel<<<(Nn * Hh + 255) / 256, 256>>>(ew1, ew2, xw1, nw1, nw2);
    edge_kernel<<<Ee / 128, 256, EDGE_SMEM>>>(h, x, ea, eb1, eb2,
                                              infw, infb, xb1, xw2, xb2, eidx);
    node_kernel<<<(Nn + 127) / 128, 256, NODE_SMEM>>>(h, x, nb1, nb2, out);
}